// round 14
// baseline (speedup 1.0000x reference)
#include <cuda_runtime.h>
#include <cuda_fp16.h>
#include <cstdint>

#define TILE_N 32
#define THREADS 256
#define XH 1032            // x_h row stride in halves (2064 B, 16B-aligned; 516 w ≡ 4 mod 32)
#define XSF 1028           // scratch fp32 row stride (words)
#define OST_MAX 452        // out-stage row stride for lo=3 (64*7+4)

__device__ __forceinline__ unsigned pack_h2(float lo, float hi) {
    unsigned d; asm("cvt.rn.f16x2.f32 %0, %1, %2;" : "=r"(d) : "f"(hi), "f"(lo)); return d;
}
__device__ __forceinline__ void cp16(float* dst, const float* src) {
    unsigned d = (unsigned)__cvta_generic_to_shared(dst);
    asm volatile("cp.async.cg.shared.global [%0], [%1], 16;" :: "r"(d), "l"(src));
}
__device__ __forceinline__ void cp_commit() {
    asm volatile("cp.async.commit_group;" ::: "memory");
}
__device__ __forceinline__ void cp_wait0() {
    asm volatile("cp.async.wait_group 0;" ::: "memory");
}
__device__ __forceinline__ void cp_wait1() {
    asm volatile("cp.async.wait_group 1;" ::: "memory");
}

// non-volatile: pure dataflow
#define MMA16(C, A0, A1, A2, A3, B0, B1)                                       \
    asm("mma.sync.aligned.m16n8k16.row.col.f32.f16.f16.f32 "                   \
        "{%0,%1,%2,%3}, {%4,%5,%6,%7}, {%8,%9}, {%0,%1,%2,%3};"                \
        : "+f"((C)[0]), "+f"((C)[1]), "+f"((C)[2]), "+f"((C)[3])               \
        : "r"(A0), "r"(A1), "r"(A2), "r"(A3), "r"(B0), "r"(B1))

#define LDSM4(A0, A1, A2, A3, ADDR)                                            \
    asm("ldmatrix.sync.aligned.m8n8.x4.shared.b16 {%0,%1,%2,%3}, [%4];"        \
        : "=r"(A0), "=r"(A1), "=r"(A2), "=r"(A3) : "r"(ADDR))

// channel MMA: T[2][4] += x[channel] @ W ; A via ldmatrix.x4 (4 LDSM per channel)
#define RAW_CH(T, CB)                                                           \
    do {                                                                        \
        _Pragma("unroll")                                                       \
        for (int ks = 0; ks < 4; ++ks) {                                        \
            unsigned a0, a1, a2, a3;                                            \
            LDSM4(a0, a1, a2, a3, xsm + (CB) + 32 * ks);                        \
            MMA16(T[0], a0, a1, a2, a3, bw[0][ks][0], bw[0][ks][1]);            \
            MMA16(T[1], a0, a1, a2, a3, bw[1][ks][0], bw[1][ks][1]);            \
        }                                                                       \
    } while (0)

#define ZERO2x4(T) do {                                                        \
    T[0][0]=T[0][1]=T[0][2]=T[0][3]=0.f;                                       \
    T[1][0]=T[1][1]=T[1][2]=T[1][3]=0.f; } while (0)

__global__ __launch_bounds__(THREADS, 1)
void tp_kernel(const float* __restrict__ x, const float* __restrict__ W,
               const float* __restrict__ hzero, const float* __restrict__ hpos,
               const float* __restrict__ hneg, float* __restrict__ out)
{
    extern __shared__ float smem[];
    __half* x_h = (__half*)smem;                        // 32*XH halves = 66048 B
    float*  scr = (float*)((char*)smem + 32 * XH * 2);  // 2 chunks * 8*XSF = 65792 B
    float*  o_s = scr;                                  // o_s reuses scr region (57856 B)

    const int tid = threadIdx.x;
    const long long n0 = (long long)blockIdx.x * TILE_N;
    const float* xg = x + n0 * 1024;

    // ---- prologue: x via pipelined 8-row fp32 chunks -> fp16 channel-major transpose ----
    {
        #pragma unroll
        for (int q0 = 0; q0 < 8; ++q0) {
            int q = tid + q0 * THREADS;                // 2048 float4 per chunk
            cp16(scr + (q >> 8) * XSF + ((q & 255) << 2), xg + q * 4);
        }
        cp_commit();

        for (int k = 0; k < 4; ++k) {
            if (k < 3) {
                float* dst = scr + ((k + 1) & 1) * (8 * XSF);
                const float* src = xg + (k + 1) * 8192;
                #pragma unroll
                for (int q0 = 0; q0 < 8; ++q0) {
                    int q = tid + q0 * THREADS;
                    cp16(dst + (q >> 8) * XSF + ((q & 255) << 2), src + q * 4);
                }
                cp_commit();
                cp_wait1();
            } else {
                cp_wait0();
            }
            __syncthreads();                           // chunk k visible to all
            const float* sb = scr + (k & 1) * (8 * XSF);
            #pragma unroll
            for (int bi = 0; bi < 4; ++bi) {
                const int si = 2 * bi + 1, basef = 64 * bi * bi;
                const int cnt = 512 * si;              // 8 rows * 64 * si
                for (int q = tid; q < cnt; q += THREADS) {
                    int i = q & 63, rc = q >> 6;
                    int c = rc % si, r = rc / si;
                    float v = sb[r * XSF + basef + i * si + c];
                    x_h[(8 * k + r) * XH + basef + c * 64 + i] = __float2half_rn(v);
                }
            }
            __syncthreads();                           // transpose reads done before chunk overwrite
        }
    }

    const int warp = tid >> 5, lane = tid & 31;
    const int wm = warp >> 2, wn = warp & 3;       // 2 (M) x 4 (N) warp grid
    const int g  = lane >> 2, t4 = lane & 3;
    const int r0 = wm * 16 + g;

    // ldmatrix lane base address: grp 0..3 -> (rows 0-7, 8-15) x (k0, k8)
    const int grp = lane >> 3;
    const int lrow = wm * 16 + ((grp & 1) << 3) + (lane & 7);
    const int lkof = (grp >> 1) << 3;
    const unsigned xsm = (unsigned)__cvta_generic_to_shared(x_h + lrow * XH + lkof);

    #pragma unroll
    for (int oi = 0; oi < 4; ++oi) {
        const int lo = oi, so = 2 * oi + 1;
        const int offo = 64 * oi * oi;
        const int ost = 64 * so + 4;

        float acc[2][7][4];
        #pragma unroll
        for (int nt = 0; nt < 2; ++nt)
            #pragma unroll
            for (int co = 0; co <= 2 * oi; ++co) {
                acc[nt][co][0] = 0.f; acc[nt][co][1] = 0.f;
                acc[nt][co][2] = 0.f; acc[nt][co][3] = 0.f;
            }

        #pragma unroll
        for (int ii = 0; ii < 4; ++ii) {
            const int bhb = 128 * ii * ii;             // block base, bytes in x_h
            const int p = (oi << 2) + ii;

            // ---- B (W) fragments straight from global: coalesced LDG.64, L1/L2-hot ----
            unsigned bw[2][4][2];
            {
                const float* Wp = W + p * 4096 + (wn * 16 + g) * 64 + 2 * t4;
                #pragma unroll
                for (int nt = 0; nt < 2; ++nt)
                    #pragma unroll
                    for (int ks = 0; ks < 4; ++ks) {
                        float2 f0 = *(const float2*)(Wp + nt * 512 + 16 * ks);
                        float2 f1 = *(const float2*)(Wp + nt * 512 + 16 * ks + 8);
                        bw[nt][ks][0] = pack_h2(f0.x, f0.y);
                        bw[nt][ks][1] = pack_h2(f1.x, f1.y);
                    }
            }

            const float h0 = __ldg(hzero + p);

            // ---- m = 0: raw x[li] @ W, scale by h0 into acc ----
            {
                float t[2][4];
                ZERO2x4(t);
                RAW_CH(t, bhb + 128 * ii);             // channel c = li
                #pragma unroll
                for (int nt = 0; nt < 2; ++nt)
                    #pragma unroll
                    for (int j = 0; j < 4; ++j)
                        acc[nt][lo][j] = fmaf(h0, t[nt][j], acc[nt][lo][j]);
            }

            // ---- m >= 1: raw xp@W, xn@W; rotate once per m in fp32 ----
            #pragma unroll
            for (int m = 1; m <= oi; ++m) {
                if (ii >= m) {
                    float tp[2][4], tn[2][4];
                    ZERO2x4(tp); ZERO2x4(tn);
                    RAW_CH(tp, bhb + 128 * (ii + m));  // channel li+m
                    RAW_CH(tn, bhb + 128 * (ii - m));  // channel li-m
                    const float hp = __ldg(hpos + p * 3 + m - 1);
                    const float hn = __ldg(hneg + p * 3 + m - 1);
                    #pragma unroll
                    for (int nt = 0; nt < 2; ++nt)
                        #pragma unroll
                        for (int j = 0; j < 4; ++j) {
                            acc[nt][lo + m][j] = fmaf(hp, tp[nt][j],
                                                 fmaf(hn, tn[nt][j], acc[nt][lo + m][j]));
                            acc[nt][lo - m][j] = fmaf(hp, tn[nt][j],
                                                 fmaf(-hn, tp[nt][j], acc[nt][lo - m][j]));
                        }
                }
            }
        }

        // ---- epilogue: regs -> interleaved stage -> coalesced float4 global ----
        #pragma unroll
        for (int nt = 0; nt < 2; ++nt) {
            int o0 = wn * 16 + nt * 8 + 2 * t4;
            #pragma unroll
            for (int co = 0; co <= 2 * oi; ++co) {
                float* d0 = o_s + r0 * ost + o0 * so + co;
                float* d1 = d0 + 8 * ost;
                d0[0]  = acc[nt][co][0];
                d0[so] = acc[nt][co][1];
                d1[0]  = acc[nt][co][2];
                d1[so] = acc[nt][co][3];
            }
        }
        __syncthreads();
        {
            const int nf4 = 16 * so;
            for (int q = tid; q < TILE_N * nf4; q += THREADS) {
                int r = q / nf4, c = q - r * nf4;
                float4 v = *(const float4*)(o_s + r * ost + (c << 2));
                *(float4*)(out + (n0 + r) * 1024 + offo + (c << 2)) = v;
            }
        }
        __syncthreads();   // copy-out done before next oi's stage writes
    }
}

extern "C" void kernel_launch(void* const* d_in, const int* in_sizes, int n_in,
                              void* d_out, int out_size) {
    const float* x  = (const float*)d_in[0];
    const float* w  = (const float*)d_in[1];
    const float* hz = (const float*)d_in[2];
    const float* hp = (const float*)d_in[3];
    const float* hn = (const float*)d_in[4];
    float* out = (float*)d_out;

    const int n = in_sizes[0] / 1024;              // 65536
    const int grid = n / TILE_N;                   // 2048
    const int smem_bytes = 32 * XH * 2 + 2 * (8 * XSF) * 4;   // 66048 + 65792 = 131840 B

    cudaFuncSetAttribute(tp_kernel, cudaFuncAttributeMaxDynamicSharedMemorySize, smem_bytes);
    tp_kernel<<<grid, THREADS, smem_bytes>>>(x, w, hz, hp, hn, out);
}

// round 16
// speedup vs baseline: 1.3247x; 1.3247x over previous
#include <cuda_runtime.h>
#include <cuda_fp16.h>
#include <cstdint>

#define TILE_N 32
#define THREADS 256
#define XH 1032            // x_h row stride in halves (2064 B: 16B-aligned, 516 w ≡ 4 mod 32)
#define XSF 1028           // scratch fp32 row stride (words)
#define WS 72              // w_s row stride (floats) ≡ 8 mod 32 -> conflict-free LDS.64 B reads
#define WBUF (64 * WS)     // 4608 floats per W buffer
#define OST_MAX 452        // out-stage row stride for lo=3 (64*7+4)

__device__ __forceinline__ unsigned pack_h2(float lo, float hi) {
    unsigned d; asm("cvt.rn.f16x2.f32 %0, %1, %2;" : "=r"(d) : "f"(hi), "f"(lo)); return d;
}
__device__ __forceinline__ void cp16(float* dst, const float* src) {
    unsigned d = (unsigned)__cvta_generic_to_shared(dst);
    asm volatile("cp.async.cg.shared.global [%0], [%1], 16;" :: "r"(d), "l"(src));
}
__device__ __forceinline__ void cp_commit() {
    asm volatile("cp.async.commit_group;" ::: "memory");
}
__device__ __forceinline__ void cp_wait0() {
    asm volatile("cp.async.wait_group 0;" ::: "memory");
}
__device__ __forceinline__ void cp_wait1() {
    asm volatile("cp.async.wait_group 1;" ::: "memory");
}

// non-volatile: pure dataflow, ptxas may interleave
#define MMA16(C, A0, A1, A2, A3, B0, B1)                                       \
    asm("mma.sync.aligned.m16n8k16.row.col.f32.f16.f16.f32 "                   \
        "{%0,%1,%2,%3}, {%4,%5,%6,%7}, {%8,%9}, {%0,%1,%2,%3};"                \
        : "+f"((C)[0]), "+f"((C)[1]), "+f"((C)[2]), "+f"((C)[3])               \
        : "r"(A0), "r"(A1), "r"(A2), "r"(A3), "r"(B0), "r"(B1))

#define LDSM4(A0, A1, A2, A3, ADDR)                                            \
    asm("ldmatrix.sync.aligned.m8n8.x4.shared.b16 {%0,%1,%2,%3}, [%4];"        \
        : "=r"(A0), "=r"(A1), "=r"(A2), "=r"(A3) : "r"(ADDR))

// channel MMA: T[2][4] += x[channel] @ W ; A via ldmatrix.x4 (layout verified R13)
#define RAW_CH(T, CB)                                                           \
    do {                                                                        \
        _Pragma("unroll")                                                       \
        for (int ks = 0; ks < 4; ++ks) {                                        \
            unsigned a0, a1, a2, a3;                                            \
            LDSM4(a0, a1, a2, a3, xsm + (CB) + 32 * ks);                        \
            MMA16(T[0], a0, a1, a2, a3, bw[0][ks][0], bw[0][ks][1]);            \
            MMA16(T[1], a0, a1, a2, a3, bw[1][ks][0], bw[1][ks][1]);            \
        }                                                                       \
    } while (0)

#define ZERO2x4(T) do {                                                        \
    T[0][0]=T[0][1]=T[0][2]=T[0][3]=0.f;                                       \
    T[1][0]=T[1][1]=T[1][2]=T[1][3]=0.f; } while (0)

__global__ __launch_bounds__(THREADS, 1)
void tp_kernel(const float* __restrict__ x, const float* __restrict__ W,
               const float* __restrict__ hzero, const float* __restrict__ hpos,
               const float* __restrict__ hneg, float* __restrict__ out)
{
    extern __shared__ float smem[];
    __half* x_h = (__half*)smem;                        // 32*XH halves = 66048 B
    float*  w_s = (float*)((char*)smem + 32 * XH * 2);  // 2*WBUF floats = 36864 B
    float*  o_s = w_s + 2 * WBUF;                       // 32*OST_MAX floats = 57856 B
    float*  scr = w_s + WBUF;                           // transpose scratch (wbuf1 + o_s region)

    const int tid = threadIdx.x;
    const long long n0 = (long long)blockIdx.x * TILE_N;
    const float* xg = x + n0 * 1024;

    // ---- prologue: W0 cp.async; x via pipelined 8-row chunks -> fp16 transpose ----
    {
        #pragma unroll
        for (int q0 = 0; q0 < 4; ++q0) {
            int q = tid + q0 * THREADS;
            cp16(w_s + (q >> 4) * WS + ((q & 15) << 2), W + q * 4);
        }
        cp_commit();                                   // group: W0
        #pragma unroll
        for (int q0 = 0; q0 < 8; ++q0) {
            int q = tid + q0 * THREADS;                // 2048 float4 per chunk
            cp16(scr + (q >> 8) * XSF + ((q & 255) << 2), xg + q * 4);
        }
        cp_commit();                                   // group: chunk 0

        for (int k = 0; k < 4; ++k) {
            if (k < 3) {
                float* dst = scr + ((k + 1) & 1) * (8 * XSF);
                const float* src = xg + (k + 1) * 8192;
                #pragma unroll
                for (int q0 = 0; q0 < 8; ++q0) {
                    int q = tid + q0 * THREADS;
                    cp16(dst + (q >> 8) * XSF + ((q & 255) << 2), src + q * 4);
                }
                cp_commit();
                cp_wait1();
            } else {
                cp_wait0();
            }
            __syncthreads();                           // chunk k visible to all
            const float* sb = scr + (k & 1) * (8 * XSF);
            #pragma unroll
            for (int bi = 0; bi < 4; ++bi) {
                const int si = 2 * bi + 1, basef = 64 * bi * bi;
                const int cnt = 512 * si;              // 8 rows * 64 * si
                for (int q = tid; q < cnt; q += THREADS) {
                    int i = q & 63, rc = q >> 6;
                    int c = rc % si, r = rc / si;
                    float v = sb[r * XSF + basef + i * si + c];
                    x_h[(8 * k + r) * XH + basef + c * 64 + i] = __float2half_rn(v);
                }
            }
        }
    }

    const int warp = tid >> 5, lane = tid & 31;
    const int wm = warp >> 2, wn = warp & 3;       // 2 (M) x 4 (N) warp grid
    const int g  = lane >> 2, t4 = lane & 3;
    const int r0 = wm * 16 + g;

    // ldmatrix lane base: grp 0..3 -> (rows 0-7, 8-15) x (k0, k8)  [verified R13]
    const int grp = lane >> 3;
    const int lrow = wm * 16 + ((grp & 1) << 3) + (lane & 7);
    const int lkof = (grp >> 1) << 3;
    const unsigned xsm = (unsigned)__cvta_generic_to_shared(x_h + lrow * XH + lkof);

    #pragma unroll
    for (int oi = 0; oi < 4; ++oi) {
        const int lo = oi, so = 2 * oi + 1;
        const int offo = 64 * oi * oi;
        const int ost = 64 * so + 4;

        float acc[2][7][4];
        #pragma unroll
        for (int nt = 0; nt < 2; ++nt)
            #pragma unroll
            for (int co = 0; co <= 2 * oi; ++co) {
                acc[nt][co][0] = 0.f; acc[nt][co][1] = 0.f;
                acc[nt][co][2] = 0.f; acc[nt][co][3] = 0.f;
            }

        #pragma unroll
        for (int ii = 0; ii < 4; ++ii) {
            const int bhb = 128 * ii * ii;             // block base, bytes in x_h
            const int p = (oi << 2) + ii;

            cp_wait0();          // W_p staged (this thread)
            __syncthreads();     // all copies visible; prior path done with both buffers

            if (p < 15) {        // prefetch next path's W into the other buffer
                const float* Wn = W + (p + 1) * 4096;
                float* wd = w_s + ((p + 1) & 1) * WBUF;
                #pragma unroll
                for (int q0 = 0; q0 < 4; ++q0) {
                    int q = tid + q0 * THREADS;
                    cp16(wd + (q >> 4) * WS + ((q & 15) << 2), Wn + q * 4);
                }
                cp_commit();
            }

            // ---- B (W) fragments: fp32 LDS.64 pair -> packed half2 ----
            unsigned bw[2][4][2];
            {
                const float* wb = w_s + (p & 1) * WBUF + (wn * 16 + g) * WS + 2 * t4;
                #pragma unroll
                for (int nt = 0; nt < 2; ++nt)
                    #pragma unroll
                    for (int ks = 0; ks < 4; ++ks) {
                        float2 f0 = *(const float2*)(wb + nt * 8 * WS + 16 * ks);
                        float2 f1 = *(const float2*)(wb + nt * 8 * WS + 16 * ks + 8);
                        bw[nt][ks][0] = pack_h2(f0.x, f0.y);
                        bw[nt][ks][1] = pack_h2(f1.x, f1.y);
                    }
            }

            const float h0 = __ldg(hzero + p);

            // ---- m = 0: raw x[li] @ W, scale by h0 into acc ----
            {
                float t[2][4];
                ZERO2x4(t);
                RAW_CH(t, bhb + 128 * ii);             // channel c = li
                #pragma unroll
                for (int nt = 0; nt < 2; ++nt)
                    #pragma unroll
                    for (int j = 0; j < 4; ++j)
                        acc[nt][lo][j] = fmaf(h0, t[nt][j], acc[nt][lo][j]);
            }

            // ---- m >= 1: raw xp@W, xn@W; rotate once per m in fp32 ----
            #pragma unroll
            for (int m = 1; m <= oi; ++m) {
                if (ii >= m) {
                    float tp[2][4], tn[2][4];
                    ZERO2x4(tp); ZERO2x4(tn);
                    RAW_CH(tp, bhb + 128 * (ii + m));  // channel li+m
                    RAW_CH(tn, bhb + 128 * (ii - m));  // channel li-m
                    const float hp = __ldg(hpos + p * 3 + m - 1);
                    const float hn = __ldg(hneg + p * 3 + m - 1);
                    #pragma unroll
                    for (int nt = 0; nt < 2; ++nt)
                        #pragma unroll
                        for (int j = 0; j < 4; ++j) {
                            acc[nt][lo + m][j] = fmaf(hp, tp[nt][j],
                                                 fmaf(hn, tn[nt][j], acc[nt][lo + m][j]));
                            acc[nt][lo - m][j] = fmaf(hp, tn[nt][j],
                                                 fmaf(-hn, tp[nt][j], acc[nt][lo - m][j]));
                        }
                }
            }
        }

        // ---- epilogue: regs -> interleaved stage -> coalesced float4 global ----
        // (prior oi's o_s reads fenced by this oi's ii=0 barrier)
        #pragma unroll
        for (int nt = 0; nt < 2; ++nt) {
            int o0 = wn * 16 + nt * 8 + 2 * t4;
            #pragma unroll
            for (int co = 0; co <= 2 * oi; ++co) {
                float* d0 = o_s + r0 * ost + o0 * so + co;
                float* d1 = d0 + 8 * ost;
                d0[0]  = acc[nt][co][0];
                d0[so] = acc[nt][co][1];
                d1[0]  = acc[nt][co][2];
                d1[so] = acc[nt][co][3];
            }
        }
        __syncthreads();
        {
            const int nf4 = 16 * so;
            for (int q = tid; q < TILE_N * nf4; q += THREADS) {
                int r = q / nf4, c = q - r * nf4;
                float4 v = *(const float4*)(o_s + r * ost + (c << 2));
                *(float4*)(out + (n0 + r) * 1024 + offo + (c << 2)) = v;
            }
        }
    }
}

extern "C" void kernel_launch(void* const* d_in, const int* in_sizes, int n_in,
                              void* d_out, int out_size) {
    const float* x  = (const float*)d_in[0];
    const float* w  = (const float*)d_in[1];
    const float* hz = (const float*)d_in[2];
    const float* hp = (const float*)d_in[3];
    const float* hn = (const float*)d_in[4];
    float* out = (float*)d_out;

    const int n = in_sizes[0] / 1024;              // 65536
    const int grid = n / TILE_N;                   // 2048
    const int smem_bytes = 32 * XH * 2 + 2 * WBUF * 4 + TILE_N * OST_MAX * 4; // 160768 B

    cudaFuncSetAttribute(tp_kernel, cudaFuncAttributeMaxDynamicSharedMemorySize, smem_bytes);
    tp_kernel<<<grid, THREADS, smem_bytes>>>(x, w, hz, hp, hn, out);
}